// round 12
// baseline (speedup 1.0000x reference)
#include <cuda_runtime.h>
#include <math.h>

#define N_ENT   150000
#define N_USR   60000
#define CDIM    64
#define NE      1000000
#define NNZV    1000000
#define NRELM1  9

// concat degree/offset layout: [edges-by-head (N_ENT) | inter-by-col (N_ENT) | inter-by-row (N_USR)]
#define NT          (N_ENT + N_ENT + N_USR)   // 360000
#define SCAN_TILE   1024
#define SCAN_BLOCKS ((NT + SCAN_TILE - 1) / SCAN_TILE)  // 352

// ---------------- scratch (static device globals; no allocation) ----------------
__device__ float g_entA[(size_t)N_ENT * CDIM];
__device__ float g_usrA[(size_t)N_USR * CDIM];
__device__ float g_entB[(size_t)N_ENT * CDIM];
__device__ float g_usrB[(size_t)N_USR * CDIM];
__device__ float g_sq[NRELM1 * N_ENT];        // ||ent ∘ w_r||^2 (5.4 MB, L2-resident)

__device__ int g_deg[NT];
__device__ int g_off[NT + 1];
__device__ int g_cursor[NT];
__device__ int g_bsum[SCAN_BLOCKS];
__device__ int   g_epack[NE];                 // (tail << 4) | rel, grouped by head
__device__ int   g_nbr_e[NNZV];               // user idx, grouped by col
__device__ float g_val_e[NNZV];               // val,      grouped by col
__device__ int   g_nbr_u[NNZV];               // entity idx, grouped by row
__device__ float g_val_u[NNZV];               // val,        grouped by row

// ---------------- init: curA = emb, out(residual) = emb, deg = 0 ----------------
__global__ void k_init(const float* __restrict__ ue,
                       const float* __restrict__ ee,
                       float* __restrict__ out) {
    const int tot_e = N_ENT * CDIM / 4;
    const int tot_u = N_USR * CDIM / 4;
    float4* ec = (float4*)g_entA;
    float4* uc = (float4*)g_usrA;
    float4* oe = (float4*)out;
    float4* ou = (float4*)(out + (size_t)N_ENT * CDIM);
    const float4* e4 = (const float4*)ee;
    const float4* u4 = (const float4*)ue;
    int stride = gridDim.x * blockDim.x;
    int i0 = blockIdx.x * blockDim.x + threadIdx.x;
    for (int i = i0; i < tot_e; i += stride) { float4 v = e4[i]; ec[i] = v; oe[i] = v; }
    for (int i = i0; i < tot_u; i += stride) { float4 v = u4[i]; uc[i] = v; ou[i] = v; }
    for (int i = i0; i < NT;    i += stride) g_deg[i] = 0;
}

// ---------------- CSR build: histogram ----------------
__global__ void k_hist(const int* __restrict__ head,
                       const int* __restrict__ rows, const int* __restrict__ cols) {
    int i = blockIdx.x * blockDim.x + threadIdx.x;
    if (i >= NE) return;                       // NE == NNZV
    atomicAdd(&g_deg[head[i]], 1);
    atomicAdd(&g_deg[N_ENT + cols[i]], 1);
    atomicAdd(&g_deg[2 * N_ENT + rows[i]], 1);
}

// ---------------- CSR build: 3-kernel exclusive grid scan over g_deg ----------------
__global__ void k_scan1() {
    __shared__ int sh[256];
    int b = blockIdx.x, t = threadIdx.x;
    int base = b * SCAN_TILE + t * 4;
    int v0 = (base + 0 < NT) ? g_deg[base + 0] : 0;
    int v1 = (base + 1 < NT) ? g_deg[base + 1] : 0;
    int v2 = (base + 2 < NT) ? g_deg[base + 2] : 0;
    int v3 = (base + 3 < NT) ? g_deg[base + 3] : 0;
    int tsum = v0 + v1 + v2 + v3;
    sh[t] = tsum;
    __syncthreads();
    #pragma unroll
    for (int o = 1; o < 256; o <<= 1) {
        int x = (t >= o) ? sh[t - o] : 0;
        __syncthreads();
        sh[t] += x;
        __syncthreads();
    }
    int excl = sh[t] - tsum;
    if (t == 255) g_bsum[b] = sh[255];
    if (base + 0 < NT) g_off[base + 0] = excl;          excl += v0;
    if (base + 1 < NT) g_off[base + 1] = excl;          excl += v1;
    if (base + 2 < NT) g_off[base + 2] = excl;          excl += v2;
    if (base + 3 < NT) g_off[base + 3] = excl;
}

__global__ void k_scan2() {
    __shared__ int sh[512];
    int t = threadIdx.x;
    int v = (t < SCAN_BLOCKS) ? g_bsum[t] : 0;
    sh[t] = v;
    __syncthreads();
    #pragma unroll
    for (int o = 1; o < 512; o <<= 1) {
        int x = (t >= o) ? sh[t - o] : 0;
        __syncthreads();
        sh[t] += x;
        __syncthreads();
    }
    if (t < SCAN_BLOCKS) g_bsum[t] = sh[t] - v;   // exclusive
}

__global__ void k_scan3() {
    int i = blockIdx.x * blockDim.x + threadIdx.x;
    if (i >= NT) return;
    int v = g_off[i] + g_bsum[i / SCAN_TILE];
    g_off[i] = v;
    g_cursor[i] = v;
    if (i == 0) g_off[NT] = NE + 2 * NNZV;
}

// ---------------- CSR build: fill payload arrays (sequential at read time) ---------
__global__ void k_fill(const int* __restrict__ head, const int* __restrict__ tail,
                       const int* __restrict__ etype,
                       const int* __restrict__ rows, const int* __restrict__ cols,
                       const float* __restrict__ vals) {
    int i = blockIdx.x * blockDim.x + threadIdx.x;
    if (i >= NE) return;
    int r = etype[i] - 1;
    if (r < 0) r += NRELM1;                    // JAX wrap: -1 -> 8
    int p0 = atomicAdd(&g_cursor[head[i]], 1);
    g_epack[p0] = (tail[i] << 4) | r;
    float v = vals[i];
    int p1 = atomicAdd(&g_cursor[N_ENT + cols[i]], 1) - NE;
    g_nbr_e[p1] = rows[i];
    g_val_e[p1] = v;
    int p2 = atomicAdd(&g_cursor[2 * N_ENT + rows[i]], 1) - NE - NNZV;
    g_nbr_u[p2] = cols[i];
    g_val_u[p2] = v;
}

// ---------------- per-hop: g_sq[r][ent] = ||ent ∘ w_r||^2 (16 lanes/row) ------------
__global__ void k_sq(int hop, const float* __restrict__ weight) {
    const float* ent = hop ? g_entB : g_entA;
    int idx  = blockIdx.x * blockDim.x + threadIdx.x;
    int row  = idx >> 4;
    int lane = idx & 15;
    if (row >= N_ENT) return;
    float4 x = ((const float4*)(ent + (size_t)row * CDIM))[lane];
    float mine = 0.f;
    #pragma unroll
    for (int r = 0; r < NRELM1; r++) {
        float4 rv = ((const float4*)(weight + (size_t)r * CDIM))[lane];
        float a0 = x.x * rv.x, a1 = x.y * rv.y, a2 = x.z * rv.z, a3 = x.w * rv.w;
        float p = a0 * a0 + a1 * a1 + a2 * a2 + a3 * a3;
        #pragma unroll
        for (int o = 8; o; o >>= 1) p += __shfl_xor_sync(0xffffffffu, p, o);
        if (lane == r) mine = p;
    }
    if (lane < NRELM1) g_sq[lane * N_ENT + row] = mine;
}

// ---------------- per-hop: fused gather + softmax + SpMM + normalize + residual --------
// ONE FULL WARP per output row (float2 per lane): loop trip count is exactly the
// row's degree — no intra-warp divergence waste from pairing rows of different
// degree in one warp (the 16-lane scheme paid max(deg0,deg1) per loop).
// Softmax is shift-invariant and att is bounded small for this data distribution,
// so exp(att) cannot overflow; w_i = ex_i / sum factors out of the weighted sum.
__global__ void k_agg(int hop, const float* __restrict__ weight,
                      float* __restrict__ out) {
    const float* entc = hop ? g_entB : g_entA;
    const float* usrc = hop ? g_usrB : g_usrA;
    float* entn = hop ? g_entA : g_entB;
    float* usrn = hop ? g_usrA : g_usrB;

    int idx  = blockIdx.x * blockDim.x + threadIdx.x;
    int row  = idx >> 5;
    int lane = idx & 31;
    float2 acc = make_float2(0.f, 0.f);
    float* dst;
    float* ores;
    if (row < N_ENT) {
        // --- knowledge-graph edges (softmax-weighted neighbors) ---
        int s0 = g_off[row], s1 = g_off[row + 1];
        float s = 0.f;
        for (int j = s0; j < s1; j++) {
            int pk = g_epack[j];               // sequential
            int t = pk >> 4;
            int r = pk & 15;
            float ex = expf(g_sq[r * N_ENT + row] * g_sq[r * N_ENT + t]);
            s += ex;
            float2 tv = ((const float2*)(entc   + (size_t)t * CDIM))[lane];
            float2 rv = ((const float2*)(weight + (size_t)r * CDIM))[lane];
            acc.x += ex * tv.x * rv.x;
            acc.y += ex * tv.y * rv.y;
        }
        if (s > 0.f) {
            float is = 1.f / s;
            acc.x *= is; acc.y *= is;
        }
        // --- interact_mat^T @ user ---
        int i0 = g_off[N_ENT + row] - NE, i1 = g_off[N_ENT + row + 1] - NE;
        for (int j = i0; j < i1; j++) {
            int nb = g_nbr_e[j];               // sequential
            float v = g_val_e[j];              // sequential
            float2 u = ((const float2*)(usrc + (size_t)nb * CDIM))[lane];
            acc.x += v * u.x; acc.y += v * u.y;
        }
        dst  = entn + (size_t)row * CDIM;
        ores = out  + (size_t)row * CDIM;
    } else {
        int ur = row - N_ENT;
        if (ur >= N_USR) return;
        // --- interact_mat @ entity ---
        int i0 = g_off[2 * N_ENT + ur] - NE - NNZV;
        int i1 = g_off[2 * N_ENT + ur + 1] - NE - NNZV;
        for (int j = i0; j < i1; j++) {
            int nb = g_nbr_u[j];               // sequential
            float v = g_val_u[j];              // sequential
            float2 e = ((const float2*)(entc + (size_t)nb * CDIM))[lane];
            acc.x += v * e.x; acc.y += v * e.y;
        }
        dst  = usrn + (size_t)ur * CDIM;
        ores = out + (size_t)N_ENT * CDIM + (size_t)ur * CDIM;
    }
    // --- L2 normalize + residual accumulate (RMW; out stays L2-warm across hops) ---
    float ss = acc.x * acc.x + acc.y * acc.y;
    #pragma unroll
    for (int o = 16; o; o >>= 1) ss += __shfl_xor_sync(0xffffffffu, ss, o);
    float inv = 1.0f / fmaxf(sqrtf(ss), 1e-12f);
    float2 y = make_float2(acc.x * inv, acc.y * inv);
    ((float2*)dst)[lane] = y;                  // normal store: next hop's L2 working set
    float2* o2 = (float2*)ores + lane;
    float2 a = *o2;
    a.x += y.x; a.y += y.y;
    *o2 = a;
}

extern "C" void kernel_launch(void* const* d_in, const int* in_sizes, int n_in,
                              void* d_out, int out_size) {
    const float* user_emb   = (const float*)d_in[0];
    const float* entity_emb = (const float*)d_in[1];
    const float* weight     = (const float*)d_in[2];
    const float* inter_vals = (const float*)d_in[3];
    const int*   edge_index = (const int*)d_in[4];
    const int*   edge_type  = (const int*)d_in[5];
    const int*   inter_rows = (const int*)d_in[6];
    const int*   inter_cols = (const int*)d_in[7];
    float* out = (float*)d_out;

    const int* head = edge_index;
    const int* tail = edge_index + NE;

    const int WPB = 256;
    const int m_blocks    = (NE + WPB - 1) / WPB;
    const int nt_blocks   = (NT + WPB - 1) / WPB;
    const int sq_blocks   = (N_ENT * 16 + WPB - 1) / WPB;
    const int agg_blocks  = (int)(((size_t)(N_ENT + N_USR) * 32 + WPB - 1) / WPB);

    // once per launch: init + CSR build (graph is static across hops)
    k_init<<<2048, WPB>>>(user_emb, entity_emb, out);
    k_hist<<<m_blocks, WPB>>>(head, inter_rows, inter_cols);
    k_scan1<<<SCAN_BLOCKS, 256>>>();
    k_scan2<<<1, 512>>>();
    k_scan3<<<nt_blocks, WPB>>>();
    k_fill<<<m_blocks, WPB>>>(head, tail, edge_type, inter_rows, inter_cols, inter_vals);

    // hop 0: read A, write B;  hop 1: read B, write A
    for (int hop = 0; hop < 2; hop++) {
        k_sq<<<sq_blocks, WPB>>>(hop, weight);
        k_agg<<<agg_blocks, WPB>>>(hop, weight, out);
    }
}

// round 13
// speedup vs baseline: 1.3397x; 1.3397x over previous
#include <cuda_runtime.h>
#include <cuda_fp16.h>
#include <math.h>

#define N_ENT   150000
#define N_USR   60000
#define CDIM    64
#define NE      1000000
#define NNZV    1000000
#define NRELM1  9

// concat degree/offset layout: [edges-by-head (N_ENT) | inter-by-col (N_ENT) | inter-by-row (N_USR)]
#define NT          (N_ENT + N_ENT + N_USR)   // 360000
#define SCAN_TILE   1024
#define SCAN_BLOCKS ((NT + SCAN_TILE - 1) / SCAN_TILE)  // 352

// ---------------- scratch (static device globals; no allocation) ----------------
// Ping-pong embedding tables in FP16: halves the random-gather traffic (row = 128B).
__device__ __half g_entA[(size_t)N_ENT * CDIM];
__device__ __half g_usrA[(size_t)N_USR * CDIM];
__device__ __half g_entB[(size_t)N_ENT * CDIM];
__device__ __half g_usrB[(size_t)N_USR * CDIM];
__device__ float g_sq[NRELM1 * N_ENT];        // ||ent ∘ w_r||^2 (5.4 MB, L2-resident)

__device__ int g_deg[NT];
__device__ int g_off[NT + 1];
__device__ int g_cursor[NT];
__device__ int g_bsum[SCAN_BLOCKS];
__device__ int   g_epack[NE];                 // (tail << 4) | rel, grouped by head
__device__ int   g_nbr_e[NNZV];               // user idx, grouped by col
__device__ float g_val_e[NNZV];               // val,      grouped by col
__device__ int   g_nbr_u[NNZV];               // entity idx, grouped by row
__device__ float g_val_u[NNZV];               // val,        grouped by row

__device__ __forceinline__ float4 h4_to_f4(uint2 raw) {
    __half2 a = *reinterpret_cast<__half2*>(&raw.x);
    __half2 b = *reinterpret_cast<__half2*>(&raw.y);
    float2 fa = __half22float2(a);
    float2 fb = __half22float2(b);
    return make_float4(fa.x, fa.y, fb.x, fb.y);
}

__device__ __forceinline__ uint2 f4_to_h4(float4 v) {
    uint2 o;
    *reinterpret_cast<__half2*>(&o.x) = __floats2half2_rn(v.x, v.y);
    *reinterpret_cast<__half2*>(&o.y) = __floats2half2_rn(v.z, v.w);
    return o;
}

// ---------------- init: curA = half(emb), out(residual) = emb, deg = 0 ----------------
__global__ void k_init(const float* __restrict__ ue,
                       const float* __restrict__ ee,
                       float* __restrict__ out) {
    const int tot_e = N_ENT * CDIM / 4;
    const int tot_u = N_USR * CDIM / 4;
    uint2* ec = (uint2*)g_entA;
    uint2* uc = (uint2*)g_usrA;
    float4* oe = (float4*)out;
    float4* ou = (float4*)(out + (size_t)N_ENT * CDIM);
    const float4* e4 = (const float4*)ee;
    const float4* u4 = (const float4*)ue;
    int stride = gridDim.x * blockDim.x;
    int i0 = blockIdx.x * blockDim.x + threadIdx.x;
    for (int i = i0; i < tot_e; i += stride) { float4 v = e4[i]; ec[i] = f4_to_h4(v); oe[i] = v; }
    for (int i = i0; i < tot_u; i += stride) { float4 v = u4[i]; uc[i] = f4_to_h4(v); ou[i] = v; }
    for (int i = i0; i < NT;    i += stride) g_deg[i] = 0;
}

// ---------------- CSR build: histogram ----------------
__global__ void k_hist(const int* __restrict__ head,
                       const int* __restrict__ rows, const int* __restrict__ cols) {
    int i = blockIdx.x * blockDim.x + threadIdx.x;
    if (i >= NE) return;                       // NE == NNZV
    atomicAdd(&g_deg[head[i]], 1);
    atomicAdd(&g_deg[N_ENT + cols[i]], 1);
    atomicAdd(&g_deg[2 * N_ENT + rows[i]], 1);
}

// ---------------- CSR build: 3-kernel exclusive grid scan over g_deg ----------------
__global__ void k_scan1() {
    __shared__ int sh[256];
    int b = blockIdx.x, t = threadIdx.x;
    int base = b * SCAN_TILE + t * 4;
    int v0 = (base + 0 < NT) ? g_deg[base + 0] : 0;
    int v1 = (base + 1 < NT) ? g_deg[base + 1] : 0;
    int v2 = (base + 2 < NT) ? g_deg[base + 2] : 0;
    int v3 = (base + 3 < NT) ? g_deg[base + 3] : 0;
    int tsum = v0 + v1 + v2 + v3;
    sh[t] = tsum;
    __syncthreads();
    #pragma unroll
    for (int o = 1; o < 256; o <<= 1) {
        int x = (t >= o) ? sh[t - o] : 0;
        __syncthreads();
        sh[t] += x;
        __syncthreads();
    }
    int excl = sh[t] - tsum;
    if (t == 255) g_bsum[b] = sh[255];
    if (base + 0 < NT) g_off[base + 0] = excl;          excl += v0;
    if (base + 1 < NT) g_off[base + 1] = excl;          excl += v1;
    if (base + 2 < NT) g_off[base + 2] = excl;          excl += v2;
    if (base + 3 < NT) g_off[base + 3] = excl;
}

__global__ void k_scan2() {
    __shared__ int sh[512];
    int t = threadIdx.x;
    int v = (t < SCAN_BLOCKS) ? g_bsum[t] : 0;
    sh[t] = v;
    __syncthreads();
    #pragma unroll
    for (int o = 1; o < 512; o <<= 1) {
        int x = (t >= o) ? sh[t - o] : 0;
        __syncthreads();
        sh[t] += x;
        __syncthreads();
    }
    if (t < SCAN_BLOCKS) g_bsum[t] = sh[t] - v;   // exclusive
}

__global__ void k_scan3() {
    int i = blockIdx.x * blockDim.x + threadIdx.x;
    if (i >= NT) return;
    int v = g_off[i] + g_bsum[i / SCAN_TILE];
    g_off[i] = v;
    g_cursor[i] = v;
    if (i == 0) g_off[NT] = NE + 2 * NNZV;
}

// ---------------- CSR build: fill payload arrays (sequential at read time) ---------
__global__ void k_fill(const int* __restrict__ head, const int* __restrict__ tail,
                       const int* __restrict__ etype,
                       const int* __restrict__ rows, const int* __restrict__ cols,
                       const float* __restrict__ vals) {
    int i = blockIdx.x * blockDim.x + threadIdx.x;
    if (i >= NE) return;
    int r = etype[i] - 1;
    if (r < 0) r += NRELM1;                    // JAX wrap: -1 -> 8
    int p0 = atomicAdd(&g_cursor[head[i]], 1);
    g_epack[p0] = (tail[i] << 4) | r;
    float v = vals[i];
    int p1 = atomicAdd(&g_cursor[N_ENT + cols[i]], 1) - NE;
    g_nbr_e[p1] = rows[i];
    g_val_e[p1] = v;
    int p2 = atomicAdd(&g_cursor[2 * N_ENT + rows[i]], 1) - NE - NNZV;
    g_nbr_u[p2] = cols[i];
    g_val_u[p2] = v;
}

// ---------------- per-hop: g_sq[r][ent] = ||ent ∘ w_r||^2 (16 lanes/row) ------------
__global__ void k_sq(int hop, const float* __restrict__ weight) {
    const __half* ent = hop ? g_entB : g_entA;
    int idx  = blockIdx.x * blockDim.x + threadIdx.x;
    int row  = idx >> 4;
    int lane = idx & 15;
    if (row >= N_ENT) return;
    float4 x = h4_to_f4(((const uint2*)(ent + (size_t)row * CDIM))[lane]);
    float mine = 0.f;
    #pragma unroll
    for (int r = 0; r < NRELM1; r++) {
        float4 rv = ((const float4*)(weight + (size_t)r * CDIM))[lane];
        float a0 = x.x * rv.x, a1 = x.y * rv.y, a2 = x.z * rv.z, a3 = x.w * rv.w;
        float p = a0 * a0 + a1 * a1 + a2 * a2 + a3 * a3;
        #pragma unroll
        for (int o = 8; o; o >>= 1) p += __shfl_xor_sync(0xffffffffu, p, o);
        if (lane == r) mine = p;
    }
    if (lane < NRELM1) g_sq[lane * N_ENT + row] = mine;
}

// ---------------- per-hop: fused gather + softmax + SpMM + normalize + residual --------
// Structure identical to the 338us R7 kernel; ONLY change is fp16 table storage
// (gathered rows are 128B instead of 256B). Accumulation stays fp32.
__global__ void k_agg(int hop, const float* __restrict__ weight,
                      float* __restrict__ out) {
    const __half* entc = hop ? g_entB : g_entA;
    const __half* usrc = hop ? g_usrB : g_usrA;
    __half* entn = hop ? g_entA : g_entB;
    __half* usrn = hop ? g_usrA : g_usrB;

    int idx  = blockIdx.x * blockDim.x + threadIdx.x;
    int row  = idx >> 4;
    int lane = idx & 15;
    float4 acc = make_float4(0.f, 0.f, 0.f, 0.f);
    __half* dst;
    float* ores;
    if (row < N_ENT) {
        // --- knowledge-graph edges (softmax-weighted neighbors) ---
        int s0 = g_off[row], s1 = g_off[row + 1];
        float s = 0.f;
        for (int j = s0; j < s1; j++) {
            int pk = g_epack[j];               // sequential
            int t = pk >> 4;
            int r = pk & 15;
            float ex = expf(g_sq[r * N_ENT + row] * g_sq[r * N_ENT + t]);
            s += ex;
            float4 tv = h4_to_f4(((const uint2*)(entc + (size_t)t * CDIM))[lane]);
            float4 rv = ((const float4*)(weight + (size_t)r * CDIM))[lane];
            acc.x += ex * tv.x * rv.x;
            acc.y += ex * tv.y * rv.y;
            acc.z += ex * tv.z * rv.z;
            acc.w += ex * tv.w * rv.w;
        }
        if (s > 0.f) {
            float is = 1.f / s;
            acc.x *= is; acc.y *= is; acc.z *= is; acc.w *= is;
        }
        // --- interact_mat^T @ user ---
        int i0 = g_off[N_ENT + row] - NE, i1 = g_off[N_ENT + row + 1] - NE;
        for (int j = i0; j < i1; j++) {
            int nb = g_nbr_e[j];               // sequential
            float v = g_val_e[j];              // sequential
            float4 u = h4_to_f4(((const uint2*)(usrc + (size_t)nb * CDIM))[lane]);
            acc.x += v * u.x; acc.y += v * u.y; acc.z += v * u.z; acc.w += v * u.w;
        }
        dst  = entn + (size_t)row * CDIM;
        ores = out  + (size_t)row * CDIM;
    } else {
        int ur = row - N_ENT;
        if (ur >= N_USR) return;
        // --- interact_mat @ entity ---
        int i0 = g_off[2 * N_ENT + ur] - NE - NNZV;
        int i1 = g_off[2 * N_ENT + ur + 1] - NE - NNZV;
        for (int j = i0; j < i1; j++) {
            int nb = g_nbr_u[j];               // sequential
            float v = g_val_u[j];              // sequential
            float4 e = h4_to_f4(((const uint2*)(entc + (size_t)nb * CDIM))[lane]);
            acc.x += v * e.x; acc.y += v * e.y; acc.z += v * e.z; acc.w += v * e.w;
        }
        dst  = usrn + (size_t)ur * CDIM;
        ores = out + (size_t)N_ENT * CDIM + (size_t)ur * CDIM;
    }
    // --- L2 normalize + residual accumulate ---
    float ss = acc.x * acc.x + acc.y * acc.y + acc.z * acc.z + acc.w * acc.w;
    #pragma unroll
    for (int o = 8; o; o >>= 1) ss += __shfl_xor_sync(0xffffffffu, ss, o);
    float inv = 1.0f / fmaxf(sqrtf(ss), 1e-12f);
    float4 y = make_float4(acc.x * inv, acc.y * inv, acc.z * inv, acc.w * inv);
    ((uint2*)dst)[lane] = f4_to_h4(y);         // normal store: next hop's L2 working set
    float4* o4 = (float4*)ores + lane;
    float4 a = *o4;
    a.x += y.x; a.y += y.y; a.z += y.z; a.w += y.w;
    *o4 = a;
}

extern "C" void kernel_launch(void* const* d_in, const int* in_sizes, int n_in,
                              void* d_out, int out_size) {
    const float* user_emb   = (const float*)d_in[0];
    const float* entity_emb = (const float*)d_in[1];
    const float* weight     = (const float*)d_in[2];
    const float* inter_vals = (const float*)d_in[3];
    const int*   edge_index = (const int*)d_in[4];
    const int*   edge_type  = (const int*)d_in[5];
    const int*   inter_rows = (const int*)d_in[6];
    const int*   inter_cols = (const int*)d_in[7];
    float* out = (float*)d_out;

    const int* head = edge_index;
    const int* tail = edge_index + NE;

    const int WPB = 256;
    const int m_blocks    = (NE + WPB - 1) / WPB;
    const int nt_blocks   = (NT + WPB - 1) / WPB;
    const int sq_blocks   = (N_ENT * 16 + WPB - 1) / WPB;
    const int agg_blocks  = ((N_ENT + N_USR) * 16 + WPB - 1) / WPB;

    // once per launch: init + CSR build (graph is static across hops)
    k_init<<<2048, WPB>>>(user_emb, entity_emb, out);
    k_hist<<<m_blocks, WPB>>>(head, inter_rows, inter_cols);
    k_scan1<<<SCAN_BLOCKS, 256>>>();
    k_scan2<<<1, 512>>>();
    k_scan3<<<nt_blocks, WPB>>>();
    k_fill<<<m_blocks, WPB>>>(head, tail, edge_type, inter_rows, inter_cols, inter_vals);

    // hop 0: read A, write B;  hop 1: read B, write A
    for (int hop = 0; hop < 2; hop++) {
        k_sq<<<sq_blocks, WPB>>>(hop, weight);
        k_agg<<<agg_blocks, WPB>>>(hop, weight, out);
    }
}

// round 14
// speedup vs baseline: 1.3627x; 1.0171x over previous
#include <cuda_runtime.h>
#include <cuda_fp16.h>
#include <math.h>

#define N_ENT   150000
#define N_USR   60000
#define CDIM    64
#define NE      1000000
#define NNZV    1000000
#define NRELM1  9

// concat degree/offset layout: [edges-by-head (N_ENT) | inter-by-col (N_ENT) | inter-by-row (N_USR)]
#define NT          (N_ENT + N_ENT + N_USR)   // 360000
#define SCAN_TILE   1024
#define SCAN_BLOCKS ((NT + SCAN_TILE - 1) / SCAN_TILE)  // 352

// ---------------- scratch (static device globals; no allocation) ----------------
// Ping-pong embedding tables in FP16: halves the random-gather traffic (row = 128B).
__device__ __half g_entA[(size_t)N_ENT * CDIM];
__device__ __half g_usrA[(size_t)N_USR * CDIM];
__device__ __half g_entB[(size_t)N_ENT * CDIM];
__device__ __half g_usrB[(size_t)N_USR * CDIM];
__device__ float g_sq[NRELM1 * N_ENT];        // ||ent ∘ w_r||^2 (5.4 MB, L2-resident)

__device__ int g_deg[NT];
__device__ int g_off[NT + 1];
__device__ int g_cursor[NT];
__device__ int g_bsum[SCAN_BLOCKS];
__device__ int   g_epack[NE];                 // (tail << 4) | rel, grouped by head
__device__ int   g_nbr_e[NNZV];               // user idx, grouped by col
__device__ float g_val_e[NNZV];               // val,      grouped by col
__device__ int   g_nbr_u[NNZV];               // entity idx, grouped by row
__device__ float g_val_u[NNZV];               // val,        grouped by row

__device__ __forceinline__ float4 h4_to_f4(uint2 raw) {
    __half2 a = *reinterpret_cast<__half2*>(&raw.x);
    __half2 b = *reinterpret_cast<__half2*>(&raw.y);
    float2 fa = __half22float2(a);
    float2 fb = __half22float2(b);
    return make_float4(fa.x, fa.y, fb.x, fb.y);
}

__device__ __forceinline__ uint2 f4_to_h4(float4 v) {
    uint2 o;
    *reinterpret_cast<__half2*>(&o.x) = __floats2half2_rn(v.x, v.y);
    *reinterpret_cast<__half2*>(&o.y) = __floats2half2_rn(v.z, v.w);
    return o;
}

// ---------------- init: curA = half(emb), deg = 0 (out written only by k_final) --------
__global__ void k_init(const float* __restrict__ ue,
                       const float* __restrict__ ee) {
    const int tot_e = N_ENT * CDIM / 4;
    const int tot_u = N_USR * CDIM / 4;
    uint2* ec = (uint2*)g_entA;
    uint2* uc = (uint2*)g_usrA;
    const float4* e4 = (const float4*)ee;
    const float4* u4 = (const float4*)ue;
    int stride = gridDim.x * blockDim.x;
    int i0 = blockIdx.x * blockDim.x + threadIdx.x;
    for (int i = i0; i < tot_e; i += stride) ec[i] = f4_to_h4(e4[i]);
    for (int i = i0; i < tot_u; i += stride) uc[i] = f4_to_h4(u4[i]);
    for (int i = i0; i < NT;    i += stride) g_deg[i] = 0;
}

// ---------------- CSR build: histogram ----------------
__global__ void k_hist(const int* __restrict__ head,
                       const int* __restrict__ rows, const int* __restrict__ cols) {
    int i = blockIdx.x * blockDim.x + threadIdx.x;
    if (i >= NE) return;                       // NE == NNZV
    atomicAdd(&g_deg[head[i]], 1);
    atomicAdd(&g_deg[N_ENT + cols[i]], 1);
    atomicAdd(&g_deg[2 * N_ENT + rows[i]], 1);
}

// ---------------- CSR build: 3-kernel exclusive grid scan over g_deg ----------------
__global__ void k_scan1() {
    __shared__ int sh[256];
    int b = blockIdx.x, t = threadIdx.x;
    int base = b * SCAN_TILE + t * 4;
    int v0 = (base + 0 < NT) ? g_deg[base + 0] : 0;
    int v1 = (base + 1 < NT) ? g_deg[base + 1] : 0;
    int v2 = (base + 2 < NT) ? g_deg[base + 2] : 0;
    int v3 = (base + 3 < NT) ? g_deg[base + 3] : 0;
    int tsum = v0 + v1 + v2 + v3;
    sh[t] = tsum;
    __syncthreads();
    #pragma unroll
    for (int o = 1; o < 256; o <<= 1) {
        int x = (t >= o) ? sh[t - o] : 0;
        __syncthreads();
        sh[t] += x;
        __syncthreads();
    }
    int excl = sh[t] - tsum;
    if (t == 255) g_bsum[b] = sh[255];
    if (base + 0 < NT) g_off[base + 0] = excl;          excl += v0;
    if (base + 1 < NT) g_off[base + 1] = excl;          excl += v1;
    if (base + 2 < NT) g_off[base + 2] = excl;          excl += v2;
    if (base + 3 < NT) g_off[base + 3] = excl;
}

__global__ void k_scan2() {
    __shared__ int sh[512];
    int t = threadIdx.x;
    int v = (t < SCAN_BLOCKS) ? g_bsum[t] : 0;
    sh[t] = v;
    __syncthreads();
    #pragma unroll
    for (int o = 1; o < 512; o <<= 1) {
        int x = (t >= o) ? sh[t - o] : 0;
        __syncthreads();
        sh[t] += x;
        __syncthreads();
    }
    if (t < SCAN_BLOCKS) g_bsum[t] = sh[t] - v;   // exclusive
}

__global__ void k_scan3() {
    int i = blockIdx.x * blockDim.x + threadIdx.x;
    if (i >= NT) return;
    int v = g_off[i] + g_bsum[i / SCAN_TILE];
    g_off[i] = v;
    g_cursor[i] = v;
    if (i == 0) g_off[NT] = NE + 2 * NNZV;
}

// ---------------- CSR build: fill payload arrays (sequential at read time) ---------
__global__ void k_fill(const int* __restrict__ head, const int* __restrict__ tail,
                       const int* __restrict__ etype,
                       const int* __restrict__ rows, const int* __restrict__ cols,
                       const float* __restrict__ vals) {
    int i = blockIdx.x * blockDim.x + threadIdx.x;
    if (i >= NE) return;
    int r = etype[i] - 1;
    if (r < 0) r += NRELM1;                    // JAX wrap: -1 -> 8
    int p0 = atomicAdd(&g_cursor[head[i]], 1);
    g_epack[p0] = (tail[i] << 4) | r;
    float v = vals[i];
    int p1 = atomicAdd(&g_cursor[N_ENT + cols[i]], 1) - NE;
    g_nbr_e[p1] = rows[i];
    g_val_e[p1] = v;
    int p2 = atomicAdd(&g_cursor[2 * N_ENT + rows[i]], 1) - NE - NNZV;
    g_nbr_u[p2] = cols[i];
    g_val_u[p2] = v;
}

// ---------------- per-hop: g_sq[r][ent] = ||ent ∘ w_r||^2 (16 lanes/row) ------------
__global__ void k_sq(int hop, const float* __restrict__ weight) {
    const __half* ent = hop ? g_entB : g_entA;
    int idx  = blockIdx.x * blockDim.x + threadIdx.x;
    int row  = idx >> 4;
    int lane = idx & 15;
    if (row >= N_ENT) return;
    float4 x = h4_to_f4(((const uint2*)(ent + (size_t)row * CDIM))[lane]);
    float mine = 0.f;
    #pragma unroll
    for (int r = 0; r < NRELM1; r++) {
        float4 rv = ((const float4*)(weight + (size_t)r * CDIM))[lane];
        float a0 = x.x * rv.x, a1 = x.y * rv.y, a2 = x.z * rv.z, a3 = x.w * rv.w;
        float p = a0 * a0 + a1 * a1 + a2 * a2 + a3 * a3;
        #pragma unroll
        for (int o = 8; o; o >>= 1) p += __shfl_xor_sync(0xffffffffu, p, o);
        if (lane == r) mine = p;
    }
    if (lane < NRELM1) g_sq[lane * N_ENT + row] = mine;
}

// ---------------- per-hop: fused gather + softmax + SpMM + normalize ----------------
// Pure gather kernel: never touches `out` or the original embeddings — keeps
// the L2 gather working set unpolluted by cold streaming traffic.
__global__ void k_agg(int hop, const float* __restrict__ weight) {
    const __half* entc = hop ? g_entB : g_entA;
    const __half* usrc = hop ? g_usrB : g_usrA;
    __half* entn = hop ? g_entA : g_entB;
    __half* usrn = hop ? g_usrA : g_usrB;

    int idx  = blockIdx.x * blockDim.x + threadIdx.x;
    int row  = idx >> 4;
    int lane = idx & 15;
    float4 acc = make_float4(0.f, 0.f, 0.f, 0.f);
    __half* dst;
    if (row < N_ENT) {
        // --- knowledge-graph edges (softmax-weighted neighbors) ---
        int s0 = g_off[row], s1 = g_off[row + 1];
        float s = 0.f;
        for (int j = s0; j < s1; j++) {
            int pk = g_epack[j];               // sequential
            int t = pk >> 4;
            int r = pk & 15;
            float ex = expf(g_sq[r * N_ENT + row] * g_sq[r * N_ENT + t]);
            s += ex;
            float4 tv = h4_to_f4(((const uint2*)(entc + (size_t)t * CDIM))[lane]);
            float4 rv = ((const float4*)(weight + (size_t)r * CDIM))[lane];
            acc.x += ex * tv.x * rv.x;
            acc.y += ex * tv.y * rv.y;
            acc.z += ex * tv.z * rv.z;
            acc.w += ex * tv.w * rv.w;
        }
        if (s > 0.f) {
            float is = 1.f / s;
            acc.x *= is; acc.y *= is; acc.z *= is; acc.w *= is;
        }
        // --- interact_mat^T @ user ---
        int i0 = g_off[N_ENT + row] - NE, i1 = g_off[N_ENT + row + 1] - NE;
        for (int j = i0; j < i1; j++) {
            int nb = g_nbr_e[j];               // sequential
            float v = g_val_e[j];              // sequential
            float4 u = h4_to_f4(((const uint2*)(usrc + (size_t)nb * CDIM))[lane]);
            acc.x += v * u.x; acc.y += v * u.y; acc.z += v * u.z; acc.w += v * u.w;
        }
        dst = entn + (size_t)row * CDIM;
    } else {
        int ur = row - N_ENT;
        if (ur >= N_USR) return;
        // --- interact_mat @ entity ---
        int i0 = g_off[2 * N_ENT + ur] - NE - NNZV;
        int i1 = g_off[2 * N_ENT + ur + 1] - NE - NNZV;
        for (int j = i0; j < i1; j++) {
            int nb = g_nbr_u[j];               // sequential
            float v = g_val_u[j];              // sequential
            float4 e = h4_to_f4(((const uint2*)(entc + (size_t)nb * CDIM))[lane]);
            acc.x += v * e.x; acc.y += v * e.y; acc.z += v * e.z; acc.w += v * e.w;
        }
        dst = usrn + (size_t)ur * CDIM;
    }
    // --- L2 normalize ---
    float ss = acc.x * acc.x + acc.y * acc.y + acc.z * acc.z + acc.w * acc.w;
    #pragma unroll
    for (int o = 8; o; o >>= 1) ss += __shfl_xor_sync(0xffffffffu, ss, o);
    float inv = 1.0f / fmaxf(sqrtf(ss), 1e-12f);
    float4 y = make_float4(acc.x * inv, acc.y * inv, acc.z * inv, acc.w * inv);
    ((uint2*)dst)[lane] = f4_to_h4(y);         // normal store: next hop's L2 working set
}

// ---------------- final: out = emb + f32(hop0 result in B) + f32(hop1 result in A) -----
// Pure streaming kernel, runs last: cache hints are safe here.
__global__ void k_final(const float* __restrict__ ue, const float* __restrict__ ee,
                        float* __restrict__ out) {
    const int tot_e = N_ENT * CDIM / 4;
    const int tot_u = N_USR * CDIM / 4;
    const float4* e4 = (const float4*)ee;
    const float4* u4 = (const float4*)ue;
    const uint2* eb = (const uint2*)g_entB;    // hop-0 entity result
    const uint2* ea = (const uint2*)g_entA;    // hop-1 entity result
    const uint2* ub = (const uint2*)g_usrB;
    const uint2* ua = (const uint2*)g_usrA;
    float4* oe = (float4*)out;
    float4* ou = (float4*)(out + (size_t)N_ENT * CDIM);
    int stride = gridDim.x * blockDim.x;
    int i0 = blockIdx.x * blockDim.x + threadIdx.x;
    for (int i = i0; i < tot_e; i += stride) {
        float4 m = __ldcs(e4 + i);
        float4 b = h4_to_f4(eb[i]);
        float4 a = h4_to_f4(ea[i]);
        __stcs(oe + i, make_float4(m.x + b.x + a.x, m.y + b.y + a.y,
                                   m.z + b.z + a.z, m.w + b.w + a.w));
    }
    for (int i = i0; i < tot_u; i += stride) {
        float4 m = __ldcs(u4 + i);
        float4 b = h4_to_f4(ub[i]);
        float4 a = h4_to_f4(ua[i]);
        __stcs(ou + i, make_float4(m.x + b.x + a.x, m.y + b.y + a.y,
                                   m.z + b.z + a.z, m.w + b.w + a.w));
    }
}

extern "C" void kernel_launch(void* const* d_in, const int* in_sizes, int n_in,
                              void* d_out, int out_size) {
    const float* user_emb   = (const float*)d_in[0];
    const float* entity_emb = (const float*)d_in[1];
    const float* weight     = (const float*)d_in[2];
    const float* inter_vals = (const float*)d_in[3];
    const int*   edge_index = (const int*)d_in[4];
    const int*   edge_type  = (const int*)d_in[5];
    const int*   inter_rows = (const int*)d_in[6];
    const int*   inter_cols = (const int*)d_in[7];
    float* out = (float*)d_out;

    const int* head = edge_index;
    const int* tail = edge_index + NE;

    const int WPB = 256;
    const int m_blocks    = (NE + WPB - 1) / WPB;
    const int nt_blocks   = (NT + WPB - 1) / WPB;
    const int sq_blocks   = (N_ENT * 16 + WPB - 1) / WPB;
    const int agg_blocks  = ((N_ENT + N_USR) * 16 + WPB - 1) / WPB;

    // once per launch: init + CSR build (graph is static across hops)
    k_init<<<2048, WPB>>>(user_emb, entity_emb);
    k_hist<<<m_blocks, WPB>>>(head, inter_rows, inter_cols);
    k_scan1<<<SCAN_BLOCKS, 256>>>();
    k_scan2<<<1, 512>>>();
    k_scan3<<<nt_blocks, WPB>>>();
    k_fill<<<m_blocks, WPB>>>(head, tail, edge_type, inter_rows, inter_cols, inter_vals);

    // hop 0: read A, write B;  hop 1: read B, write A
    for (int hop = 0; hop < 2; hop++) {
        k_sq<<<sq_blocks, WPB>>>(hop, weight);
        k_agg<<<agg_blocks, WPB>>>(hop, weight);
    }
    // residual sum, streamed once at the end
    k_final<<<2048, WPB>>>(user_emb, entity_emb, out);
}

// round 15
// speedup vs baseline: 1.4902x; 1.0936x over previous
#include <cuda_runtime.h>
#include <cuda_fp16.h>
#include <math.h>

#define N_ENT   150000
#define N_USR   60000
#define CDIM    64
#define NE      1000000
#define NNZV    1000000
#define NRELM1  9

// concat degree/offset layout: [edges-by-head (N_ENT) | inter-by-col (N_ENT) | inter-by-row (N_USR)]
#define NT          (N_ENT + N_ENT + N_USR)   // 360000
#define SCAN_TILE   1024
#define SCAN_BLOCKS ((NT + SCAN_TILE - 1) / SCAN_TILE)  // 352

// ---------------- scratch (static device globals; no allocation) ----------------
// Ping-pong embedding tables in FP16: halves the random-gather traffic (row = 128B).
__device__ __half g_entA[(size_t)N_ENT * CDIM];
__device__ __half g_usrA[(size_t)N_USR * CDIM];
__device__ __half g_entB[(size_t)N_ENT * CDIM];
__device__ __half g_usrB[(size_t)N_USR * CDIM];
__device__ float g_sq[NRELM1 * N_ENT];        // ||ent ∘ w_r||^2 (5.4 MB, L2-resident)

__device__ int g_deg[NT];
__device__ int g_off[NT + 1];
__device__ int g_cursor[NT];
__device__ int g_bsum[SCAN_BLOCKS];
__device__ int   g_epack[NE];                 // (tail << 4) | rel, grouped by head
__device__ int   g_nbr_e[NNZV];               // user idx, grouped by col
__device__ float g_val_e[NNZV];               // val,      grouped by col
__device__ int   g_nbr_u[NNZV];               // entity idx, grouped by row
__device__ float g_val_u[NNZV];               // val,        grouped by row

__device__ __forceinline__ float4 h4_to_f4(uint2 raw) {
    __half2 a = *reinterpret_cast<__half2*>(&raw.x);
    __half2 b = *reinterpret_cast<__half2*>(&raw.y);
    float2 fa = __half22float2(a);
    float2 fb = __half22float2(b);
    return make_float4(fa.x, fa.y, fb.x, fb.y);
}

__device__ __forceinline__ uint2 f4_to_h4(float4 v) {
    uint2 o;
    *reinterpret_cast<__half2*>(&o.x) = __floats2half2_rn(v.x, v.y);
    *reinterpret_cast<__half2*>(&o.y) = __floats2half2_rn(v.z, v.w);
    return o;
}

__device__ __forceinline__ void h8_to_f8(uint4 raw, float4& a, float4& b) {
    float2 f0 = __half22float2(*reinterpret_cast<__half2*>(&raw.x));
    float2 f1 = __half22float2(*reinterpret_cast<__half2*>(&raw.y));
    float2 f2 = __half22float2(*reinterpret_cast<__half2*>(&raw.z));
    float2 f3 = __half22float2(*reinterpret_cast<__half2*>(&raw.w));
    a = make_float4(f0.x, f0.y, f1.x, f1.y);
    b = make_float4(f2.x, f2.y, f3.x, f3.y);
}

__device__ __forceinline__ uint4 f8_to_h8(float4 a, float4 b) {
    uint4 o;
    *reinterpret_cast<__half2*>(&o.x) = __floats2half2_rn(a.x, a.y);
    *reinterpret_cast<__half2*>(&o.y) = __floats2half2_rn(a.z, a.w);
    *reinterpret_cast<__half2*>(&o.z) = __floats2half2_rn(b.x, b.y);
    *reinterpret_cast<__half2*>(&o.w) = __floats2half2_rn(b.z, b.w);
    return o;
}

// ---------------- init: curA = half(emb), deg = 0 (out written only by k_final) --------
__global__ void k_init(const float* __restrict__ ue,
                       const float* __restrict__ ee) {
    const int tot_e = N_ENT * CDIM / 4;
    const int tot_u = N_USR * CDIM / 4;
    uint2* ec = (uint2*)g_entA;
    uint2* uc = (uint2*)g_usrA;
    const float4* e4 = (const float4*)ee;
    const float4* u4 = (const float4*)ue;
    int stride = gridDim.x * blockDim.x;
    int i0 = blockIdx.x * blockDim.x + threadIdx.x;
    for (int i = i0; i < tot_e; i += stride) ec[i] = f4_to_h4(e4[i]);
    for (int i = i0; i < tot_u; i += stride) uc[i] = f4_to_h4(u4[i]);
    for (int i = i0; i < NT;    i += stride) g_deg[i] = 0;
}

// ---------------- CSR build: histogram ----------------
__global__ void k_hist(const int* __restrict__ head,
                       const int* __restrict__ rows, const int* __restrict__ cols) {
    int i = blockIdx.x * blockDim.x + threadIdx.x;
    if (i >= NE) return;                       // NE == NNZV
    atomicAdd(&g_deg[head[i]], 1);
    atomicAdd(&g_deg[N_ENT + cols[i]], 1);
    atomicAdd(&g_deg[2 * N_ENT + rows[i]], 1);
}

// ---------------- CSR build: 3-kernel exclusive grid scan over g_deg ----------------
__global__ void k_scan1() {
    __shared__ int sh[256];
    int b = blockIdx.x, t = threadIdx.x;
    int base = b * SCAN_TILE + t * 4;
    int v0 = (base + 0 < NT) ? g_deg[base + 0] : 0;
    int v1 = (base + 1 < NT) ? g_deg[base + 1] : 0;
    int v2 = (base + 2 < NT) ? g_deg[base + 2] : 0;
    int v3 = (base + 3 < NT) ? g_deg[base + 3] : 0;
    int tsum = v0 + v1 + v2 + v3;
    sh[t] = tsum;
    __syncthreads();
    #pragma unroll
    for (int o = 1; o < 256; o <<= 1) {
        int x = (t >= o) ? sh[t - o] : 0;
        __syncthreads();
        sh[t] += x;
        __syncthreads();
    }
    int excl = sh[t] - tsum;
    if (t == 255) g_bsum[b] = sh[255];
    if (base + 0 < NT) g_off[base + 0] = excl;          excl += v0;
    if (base + 1 < NT) g_off[base + 1] = excl;          excl += v1;
    if (base + 2 < NT) g_off[base + 2] = excl;          excl += v2;
    if (base + 3 < NT) g_off[base + 3] = excl;
}

__global__ void k_scan2() {
    __shared__ int sh[512];
    int t = threadIdx.x;
    int v = (t < SCAN_BLOCKS) ? g_bsum[t] : 0;
    sh[t] = v;
    __syncthreads();
    #pragma unroll
    for (int o = 1; o < 512; o <<= 1) {
        int x = (t >= o) ? sh[t - o] : 0;
        __syncthreads();
        sh[t] += x;
        __syncthreads();
    }
    if (t < SCAN_BLOCKS) g_bsum[t] = sh[t] - v;   // exclusive
}

__global__ void k_scan3() {
    int i = blockIdx.x * blockDim.x + threadIdx.x;
    if (i >= NT) return;
    int v = g_off[i] + g_bsum[i / SCAN_TILE];
    g_off[i] = v;
    g_cursor[i] = v;
    if (i == 0) g_off[NT] = NE + 2 * NNZV;
}

// ---------------- CSR build: fill payload arrays (sequential at read time) ---------
__global__ void k_fill(const int* __restrict__ head, const int* __restrict__ tail,
                       const int* __restrict__ etype,
                       const int* __restrict__ rows, const int* __restrict__ cols,
                       const float* __restrict__ vals) {
    int i = blockIdx.x * blockDim.x + threadIdx.x;
    if (i >= NE) return;
    int r = etype[i] - 1;
    if (r < 0) r += NRELM1;                    // JAX wrap: -1 -> 8
    int p0 = atomicAdd(&g_cursor[head[i]], 1);
    g_epack[p0] = (tail[i] << 4) | r;
    float v = vals[i];
    int p1 = atomicAdd(&g_cursor[N_ENT + cols[i]], 1) - NE;
    g_nbr_e[p1] = rows[i];
    g_val_e[p1] = v;
    int p2 = atomicAdd(&g_cursor[2 * N_ENT + rows[i]], 1) - NE - NNZV;
    g_nbr_u[p2] = cols[i];
    g_val_u[p2] = v;
}

// ---------------- per-hop: g_sq[r][ent] = ||ent ∘ w_r||^2 (16 lanes/row) ------------
__global__ void k_sq(int hop, const float* __restrict__ weight) {
    const __half* ent = hop ? g_entB : g_entA;
    int idx  = blockIdx.x * blockDim.x + threadIdx.x;
    int row  = idx >> 4;
    int lane = idx & 15;
    if (row >= N_ENT) return;
    float4 x = h4_to_f4(((const uint2*)(ent + (size_t)row * CDIM))[lane]);
    float mine = 0.f;
    #pragma unroll
    for (int r = 0; r < NRELM1; r++) {
        float4 rv = ((const float4*)(weight + (size_t)r * CDIM))[lane];
        float a0 = x.x * rv.x, a1 = x.y * rv.y, a2 = x.z * rv.z, a3 = x.w * rv.w;
        float p = a0 * a0 + a1 * a1 + a2 * a2 + a3 * a3;
        #pragma unroll
        for (int o = 8; o; o >>= 1) p += __shfl_xor_sync(0xffffffffu, p, o);
        if (lane == r) mine = p;
    }
    if (lane < NRELM1) g_sq[lane * N_ENT + row] = mine;
}

// ---------------- per-hop: fused gather + softmax + SpMM + normalize ----------------
// 8 LANES PER ROW, uint4 (8 fp16 channels) per lane: one warp iteration covers
// 4 rows with ~the same instruction count the 16-lane version spent on 2 —
// k_agg is issue-bound, so instructions-per-row is the binding metric.
__global__ void k_agg(int hop, const float* __restrict__ weight) {
    const __half* entc = hop ? g_entB : g_entA;
    const __half* usrc = hop ? g_usrB : g_usrA;
    __half* entn = hop ? g_entA : g_entB;
    __half* usrn = hop ? g_usrA : g_usrB;

    int idx  = blockIdx.x * blockDim.x + threadIdx.x;
    int row  = idx >> 3;
    int lane = idx & 7;
    float4 acc0 = make_float4(0.f, 0.f, 0.f, 0.f);
    float4 acc1 = make_float4(0.f, 0.f, 0.f, 0.f);
    __half* dst;
    if (row < N_ENT) {
        // --- knowledge-graph edges (softmax-weighted neighbors) ---
        int s0 = g_off[row], s1 = g_off[row + 1];
        float s = 0.f;
        for (int j = s0; j < s1; j++) {
            int pk = g_epack[j];               // sequential
            int t = pk >> 4;
            int r = pk & 15;
            float ex = expf(g_sq[r * N_ENT + row] * g_sq[r * N_ENT + t]);
            s += ex;
            float4 t0, t1;
            h8_to_f8(((const uint4*)(entc + (size_t)t * CDIM))[lane], t0, t1);
            const float4* wp = (const float4*)(weight + (size_t)r * CDIM);
            float4 r0 = wp[lane * 2];
            float4 r1 = wp[lane * 2 + 1];
            acc0.x += ex * t0.x * r0.x; acc0.y += ex * t0.y * r0.y;
            acc0.z += ex * t0.z * r0.z; acc0.w += ex * t0.w * r0.w;
            acc1.x += ex * t1.x * r1.x; acc1.y += ex * t1.y * r1.y;
            acc1.z += ex * t1.z * r1.z; acc1.w += ex * t1.w * r1.w;
        }
        if (s > 0.f) {
            float is = 1.f / s;
            acc0.x *= is; acc0.y *= is; acc0.z *= is; acc0.w *= is;
            acc1.x *= is; acc1.y *= is; acc1.z *= is; acc1.w *= is;
        }
        // --- interact_mat^T @ user ---
        int i0 = g_off[N_ENT + row] - NE, i1 = g_off[N_ENT + row + 1] - NE;
        for (int j = i0; j < i1; j++) {
            int nb = g_nbr_e[j];               // sequential
            float v = g_val_e[j];              // sequential
            float4 u0, u1;
            h8_to_f8(((const uint4*)(usrc + (size_t)nb * CDIM))[lane], u0, u1);
            acc0.x += v * u0.x; acc0.y += v * u0.y; acc0.z += v * u0.z; acc0.w += v * u0.w;
            acc1.x += v * u1.x; acc1.y += v * u1.y; acc1.z += v * u1.z; acc1.w += v * u1.w;
        }
        dst = entn + (size_t)row * CDIM;
    } else {
        int ur = row - N_ENT;
        if (ur >= N_USR) return;
        // --- interact_mat @ entity ---
        int i0 = g_off[2 * N_ENT + ur] - NE - NNZV;
        int i1 = g_off[2 * N_ENT + ur + 1] - NE - NNZV;
        for (int j = i0; j < i1; j++) {
            int nb = g_nbr_u[j];               // sequential
            float v = g_val_u[j];              // sequential
            float4 e0, e1;
            h8_to_f8(((const uint4*)(entc + (size_t)nb * CDIM))[lane], e0, e1);
            acc0.x += v * e0.x; acc0.y += v * e0.y; acc0.z += v * e0.z; acc0.w += v * e0.w;
            acc1.x += v * e1.x; acc1.y += v * e1.y; acc1.z += v * e1.z; acc1.w += v * e1.w;
        }
        dst = usrn + (size_t)ur * CDIM;
    }
    // --- L2 normalize (reduce over 8 lanes) ---
    float ss = acc0.x * acc0.x + acc0.y * acc0.y + acc0.z * acc0.z + acc0.w * acc0.w
             + acc1.x * acc1.x + acc1.y * acc1.y + acc1.z * acc1.z + acc1.w * acc1.w;
    #pragma unroll
    for (int o = 4; o; o >>= 1) ss += __shfl_xor_sync(0xffffffffu, ss, o);
    float inv = 1.0f / fmaxf(sqrtf(ss), 1e-12f);
    float4 y0 = make_float4(acc0.x * inv, acc0.y * inv, acc0.z * inv, acc0.w * inv);
    float4 y1 = make_float4(acc1.x * inv, acc1.y * inv, acc1.z * inv, acc1.w * inv);
    ((uint4*)dst)[lane] = f8_to_h8(y0, y1);    // normal store: next hop's L2 working set
}

// ---------------- final: out = emb + f32(hop0 result in B) + f32(hop1 result in A) -----
__global__ void k_final(const float* __restrict__ ue, const float* __restrict__ ee,
                        float* __restrict__ out) {
    const int tot_e = N_ENT * CDIM / 4;
    const int tot_u = N_USR * CDIM / 4;
    const float4* e4 = (const float4*)ee;
    const float4* u4 = (const float4*)ue;
    const uint2* eb = (const uint2*)g_entB;    // hop-0 entity result
    const uint2* ea = (const uint2*)g_entA;    // hop-1 entity result
    const uint2* ub = (const uint2*)g_usrB;
    const uint2* ua = (const uint2*)g_usrA;
    float4* oe = (float4*)out;
    float4* ou = (float4*)(out + (size_t)N_ENT * CDIM);
    int stride = gridDim.x * blockDim.x;
    int i0 = blockIdx.x * blockDim.x + threadIdx.x;
    for (int i = i0; i < tot_e; i += stride) {
        float4 m = __ldcs(e4 + i);
        float4 b = h4_to_f4(eb[i]);
        float4 a = h4_to_f4(ea[i]);
        __stcs(oe + i, make_float4(m.x + b.x + a.x, m.y + b.y + a.y,
                                   m.z + b.z + a.z, m.w + b.w + a.w));
    }
    for (int i = i0; i < tot_u; i += stride) {
        float4 m = __ldcs(u4 + i);
        float4 b = h4_to_f4(ub[i]);
        float4 a = h4_to_f4(ua[i]);
        __stcs(ou + i, make_float4(m.x + b.x + a.x, m.y + b.y + a.y,
                                   m.z + b.z + a.z, m.w + b.w + a.w));
    }
}

extern "C" void kernel_launch(void* const* d_in, const int* in_sizes, int n_in,
                              void* d_out, int out_size) {
    const float* user_emb   = (const float*)d_in[0];
    const float* entity_emb = (const float*)d_in[1];
    const float* weight     = (const float*)d_in[2];
    const float* inter_vals = (const float*)d_in[3];
    const int*   edge_index = (const int*)d_in[4];
    const int*   edge_type  = (const int*)d_in[5];
    const int*   inter_rows = (const int*)d_in[6];
    const int*   inter_cols = (const int*)d_in[7];
    float* out = (float*)d_out;

    const int* head = edge_index;
    const int* tail = edge_index + NE;

    const int WPB = 256;
    const int m_blocks    = (NE + WPB - 1) / WPB;
    const int nt_blocks   = (NT + WPB - 1) / WPB;
    const int sq_blocks   = (N_ENT * 16 + WPB - 1) / WPB;
    const int agg_blocks  = ((N_ENT + N_USR) * 8 + WPB - 1) / WPB;

    // once per launch: init + CSR build (graph is static across hops)
    k_init<<<2048, WPB>>>(user_emb, entity_emb);
    k_hist<<<m_blocks, WPB>>>(head, inter_rows, inter_cols);
    k_scan1<<<SCAN_BLOCKS, 256>>>();
    k_scan2<<<1, 512>>>();
    k_scan3<<<nt_blocks, WPB>>>();
    k_fill<<<m_blocks, WPB>>>(head, tail, edge_type, inter_rows, inter_cols, inter_vals);

    // hop 0: read A, write B;  hop 1: read B, write A
    for (int hop = 0; hop < 2; hop++) {
        k_sq<<<sq_blocks, WPB>>>(hop, weight);
        k_agg<<<agg_blocks, WPB>>>(hop, weight);
    }
    // residual sum, streamed once at the end
    k_final<<<2048, WPB>>>(user_emb, entity_emb, out);
}